// round 5
// baseline (speedup 1.0000x reference)
#include <cuda_runtime.h>
#include <cstdint>

// ---------------------------------------------------------------------------
// NNUE forward (only the selected model e is evaluated; the reference
// computes all 16 models and selects -> 16x algorithmic cut of MLP work):
//   accum[b][:]  = sum_{j<32} embed[idx[b*32+j]][:] + main_bias      (256)
//   psqt[b]      = accum[b][0]                              (pre-activation)
//   emb          = clipped_relu(accum),  clipped_relu(x) = c + 0.1*(x-c),
//                                        c = clamp(x, -1, 127/128)
//   e  = which_model[b] + (lengths[b]/17)*4                 (0..15)
//   h1 = clipped_relu(W1[e] @ emb + b1[e])   (16)
//   h2 = clipped_relu(W2[e] @ h1  + b2[e])   (32)
//   v  = W3[e] @ h2 + b3[e]                  (1)
//   out[b] = tanh(v + psqt)
// ---------------------------------------------------------------------------

#define NNUE_B      8192
#define NNUE_L      32
#define NNUE_ACC    256

__device__ __forceinline__ long long ld_int(const void* p, int i, int is64)
{
    if (is64) return ((const long long*)p)[i];
    return (long long)((const int*)p)[i];
}

__device__ __forceinline__ float clipped_relu(float x)
{
    float c = fminf(fmaxf(x, -1.0f), 0.9921875f);   // 127/128
    return c + 0.1f * (x - c);
}

__global__ __launch_bounds__(NNUE_ACC, 8)
void nnue_kernel(const void*  __restrict__ indices,
                 const void*  __restrict__ offsets,
                 const void*  __restrict__ which_model,
                 const void*  __restrict__ lengths,
                 const float* __restrict__ embed,
                 const float* __restrict__ main_bias,
                 const float* __restrict__ W1,
                 const float* __restrict__ b1,
                 const float* __restrict__ W2,
                 const float* __restrict__ b2,
                 const float* __restrict__ W3,
                 const float* __restrict__ b3,
                 float*       __restrict__ out)
{
    __shared__ __align__(16) float s_part[4 * NNUE_ACC];  // 4 q-groups x 256 cols
    __shared__ __align__(16) float s_emb[NNUE_ACC];
    __shared__ float               s_h1[16];
    __shared__ float               s_psqt;

    const int b = blockIdx.x;
    const int t = threadIdx.x;

    // dtype sniff: offsets = arange(B)*32. As int64 the 2nd 64-bit word is
    // exactly 32; as int32 it packs {64, 96} -> != 32. Block-uniform branch.
    const int is64 = (((const long long*)offsets)[1] == 32LL) ? 1 : 0;

    // Hoist model-selection loads: issue before the gather so their memory
    // latency hides behind the gather loop.
    const int e = (int)(ld_int(which_model, b, is64) +
                        (ld_int(lengths, b, is64) / 17) * 4);

    // ---- gather-accumulate, float4-vectorized, no index-staging barrier ----
    // q = row subset (j = q, q+4, ..., q+28), c = float4 column.
    // Each thread loads its own 8 indices directly (the CTA's index slice is
    // 1-2 L1 lines; redundancy across the 64 threads sharing each index is
    // absorbed by L1). All 8 index loads issue in parallel, then 8 LDG.128
    // gathers. Each warp reads a contiguous 512B slice of one 1KB row.
    // __ldcg: keep the 109MB (L2-resident) table out of L1 so W1/W2 stay hot.
    {
        const int q = t >> 6;     // 0..3
        const int c = t & 63;     // 0..63
        const int base = b * NNUE_L + q;
        int idx[8];
        #pragma unroll
        for (int k = 0; k < 8; k++)
            idx[k] = (int)ld_int(indices, base + (k << 2), is64);
        float4 acc = make_float4(0.f, 0.f, 0.f, 0.f);
        #pragma unroll
        for (int k = 0; k < 8; k++) {
            const float4 v = __ldcg((const float4*)embed + idx[k] * 64 + c);
            acc.x += v.x; acc.y += v.y; acc.z += v.z; acc.w += v.w;
        }
        ((float4*)s_part)[q * 64 + c] = acc;
    }
    __syncthreads();

    // ---- combine partials: thread t owns final column t (conflict-free) ----
    {
        float a = __ldg(main_bias + t);
        #pragma unroll
        for (int q = 0; q < 4; q++)
            a += s_part[q * NNUE_ACC + t];
        if (t == 0) s_psqt = a;
        s_emb[t] = clipped_relu(a);
    }
    __syncthreads();

    // ---- layer 1: 16 outputs, 16 threads each (sub-warp dot products) ----
    const int o = t >> 4;    // output index 0..15
    const int l = t & 15;    // lane within the 16-thread group
    const float4* w1 = (const float4*)(W1 + (e * 16 + o) * NNUE_ACC) + l * 4;
    const float4* ev = (const float4*)s_emb + l * 4;
    float p = 0.0f;
    #pragma unroll
    for (int k = 0; k < 4; k++) {
        float4 w = __ldg(w1 + k);
        float4 x = ev[k];
        p += w.x * x.x + w.y * x.y + w.z * x.z + w.w * x.w;
    }
    #pragma unroll
    for (int off = 8; off >= 1; off >>= 1)
        p += __shfl_down_sync(0xffffffffu, p, off, 16);
    if (l == 0)
        s_h1[o] = clipped_relu(p + __ldg(b1 + e * 16 + o));
    __syncthreads();

    // ---- layer 2 + layer 3 + tanh on warp 0 ----
    if (t < 32) {
        float x = __ldg(b2 + e * 32 + t);
        const float* w2 = W2 + (e * 32 + t) * 16;
        #pragma unroll
        for (int k = 0; k < 16; k++)
            x += __ldg(w2 + k) * s_h1[k];
        float h2 = clipped_relu(x);
        float v = h2 * __ldg(W3 + e * 32 + t);
        #pragma unroll
        for (int off = 16; off >= 1; off >>= 1)
            v += __shfl_down_sync(0xffffffffu, v, off);
        if (t == 0)
            out[b] = tanhf(v + __ldg(b3 + e) + s_psqt);
    }
}

extern "C" void kernel_launch(void* const* d_in, const int* in_sizes, int n_in,
                              void* d_out, int out_size)
{
    // metadata order:
    // 0 indices (B*L int), 1 offsets (B int), 2 which_model (B int),
    // 3 lengths (B int), 4 embed_weight (F*256 f32), 5 main_bias (256 f32),
    // 6 W1 (16*16*256), 7 b1 (16*16), 8 W2 (16*32*16), 9 b2 (16*32),
    // 10 W3 (16*32), 11 b3 (16)
    const void*  indices     = d_in[0];
    const void*  offsets     = d_in[1];
    const void*  which_model = d_in[2];
    const void*  lengths     = d_in[3];
    const float* embed       = (const float*)d_in[4];
    const float* main_bias   = (const float*)d_in[5];
    const float* W1          = (const float*)d_in[6];
    const float* b1          = (const float*)d_in[7];
    const float* W2          = (const float*)d_in[8];
    const float* b2          = (const float*)d_in[9];
    const float* W3          = (const float*)d_in[10];
    const float* b3          = (const float*)d_in[11];
    float* out = (float*)d_out;

    nnue_kernel<<<NNUE_B, NNUE_ACC>>>(indices, offsets, which_model, lengths,
                                      embed, main_bias,
                                      W1, b1, W2, b2, W3, b3, out);
}